// round 7
// baseline (speedup 1.0000x reference)
#include <cuda_runtime.h>
#include <cuda_bf16.h>
#include <stdint.h>

#define RNG_MODE 3   // partitionable, bits = o0 ^ o1 (confirmed R3)

typedef unsigned long long ull;

#define NB   1024
#define SS   16
#define AA   8
#define NACT 16
#define SD   256
#define EM   256
#define NROWS (NB*SS*AA)   // 131072

// ---------------- device scratch ----------------
__device__ float g_sW1[NB*EM];
__device__ float g_v[NB];
__device__ unsigned char g_pos[NROWS];
__device__ float g_adv[NROWS];
// h1 A-fragments: [b][mblk(8)][kblk(16)][lane(32)][reg(4)] u32, hi and lo
__device__ uint32_t g_Ah[(size_t)NB*8*16*32*4];
__device__ uint32_t g_Al[(size_t)NB*8*16*32*4];
// W2 B-fragments interleaved: [kblk(16)][nblk(32)][lane(32)][{bh0,bh1,bl0,bl1}] u32
__device__ uint32_t g_B[16*32*32*4];

// ---------------- threefry2x32 (JAX exact, key(42)) ----------------
__device__ __forceinline__ uint32_t rotl(uint32_t x, int r){ return (x<<r)|(x>>(32-r)); }
__device__ __forceinline__ void threefry2x32(uint32_t c0, uint32_t c1, uint32_t &o0, uint32_t &o1){
  const uint32_t k0 = 0u, k1v = 42u, k2 = 0u ^ 42u ^ 0x1BD11BDAu;
  uint32_t x0 = c0 + k0;
  uint32_t x1 = c1 + k1v;
#define TF_R(rot) { x0 += x1; x1 = rotl(x1, rot); x1 ^= x0; }
  TF_R(13) TF_R(15) TF_R(26) TF_R(6)
  x0 += k1v; x1 += k2 + 1u;
  TF_R(17) TF_R(29) TF_R(16) TF_R(24)
  x0 += k2;  x1 += k0 + 2u;
  TF_R(13) TF_R(15) TF_R(26) TF_R(6)
  x0 += k0;  x1 += k1v + 3u;
  TF_R(17) TF_R(29) TF_R(16) TF_R(24)
  x0 += k1v; x1 += k2 + 4u;
  TF_R(13) TF_R(15) TF_R(26) TF_R(6)
  x0 += k2;  x1 += k0 + 5u;
#undef TF_R
  o0 = x0; o1 = x1;
}
__device__ __forceinline__ float bits_to_unit(uint32_t bits){
  return __uint_as_float(0x3f800000u | (bits >> 9)) - 1.0f;
}

__device__ __forceinline__ void split_bf16(float v, uint32_t &h, uint32_t &l){
  __nv_bfloat16 hb = __float2bfloat16(v);
  float lf = v - __bfloat162float(hb);
  __nv_bfloat16 lb = __float2bfloat16(lf);
  h = (uint32_t)__bfloat16_as_ushort(hb);
  l = (uint32_t)__bfloat16_as_ushort(lb);
}

__device__ __forceinline__ void mma16816(float* d, const uint32_t* a, uint32_t b0, uint32_t b1){
  asm volatile("mma.sync.aligned.m16n8k16.row.col.f32.bf16.bf16.f32 "
    "{%0,%1,%2,%3}, {%4,%5,%6,%7}, {%8,%9}, {%0,%1,%2,%3};"
    : "+f"(d[0]),"+f"(d[1]),"+f"(d[2]),"+f"(d[3])
    : "r"(a[0]),"r"(a[1]),"r"(a[2]),"r"(a[3]), "r"(b0),"r"(b1));
}

// ============ K0: W2 -> interleaved B fragments ============
__global__ void k0_prepW2(const float* __restrict__ W2){
  int idx = blockIdx.x*256 + threadIdx.x;   // 32768 = 128 kp * 256 n
  int kp = idx >> 8, n = idx & 255;
  int k = kp*2;
  float v0 = W2[k*EM + n];
  float v1 = W2[(k+1)*EM + n];
  uint32_t h0,l0,h1,l1;
  split_bf16(v0,h0,l0); split_bf16(v1,h1,l1);
  uint32_t hi = h0 | (h1<<16);
  uint32_t lo = l0 | (l1<<16);
  int kblk = kp>>3;
  int reg  = (kp>>2)&1;
  int lane = (n&7)*4 + (kp&3);
  int nblk = n>>3;
  int base = ((kblk*32+nblk)*32+lane)*4;
  g_B[base + reg]     = hi;
  g_B[base + 2 + reg] = lo;
}

// ============ K1: per-b state terms ============
__global__ void k1_state(const float* __restrict__ st, const float* __restrict__ W1,
                         const float* __restrict__ b1, const float* __restrict__ Vw1,
                         const float* __restrict__ Vb1, const float* __restrict__ Vw2,
                         const float* __restrict__ Vb2){
  int b = blockIdx.x, n = threadIdx.x;
  __shared__ float s_st[SD];
  __shared__ float red[EM];
  s_st[n] = st[b*SD + n];
  __syncthreads();
  float acc  = b1[n];
  float accv = Vb1[n];
  #pragma unroll 8
  for(int k=0;k<SD;k++){
    float sv = s_st[k];
    acc  = fmaf(sv, W1 [k*EM + n], acc);
    accv = fmaf(sv, Vw1[k*EM + n], accv);
  }
  g_sW1[b*EM + n] = acc;
  red[n] = fmaxf(accv, 0.f) * Vw2[n];
  __syncthreads();
  for(int off=128; off>0; off>>=1){
    if(n<off) red[n] += red[n+off];
    __syncthreads();
  }
  if(n==0) g_v[b] = red[0] + Vb2[0];
}

// ============ K2: RNG + perms + prefix layer-1 -> A fragments (uint4 stores) ============
__global__ void k2_layer1(const float* __restrict__ qs, const float* __restrict__ W1){
  int b = blockIdx.x;
  int tid = threadIdx.x;
  __shared__ int   s_inv[SS][AA];
  __shared__ float s_rq[SS*AA*NACT];

  if(tid < SS){
    int s = tid;
    unsigned base = (unsigned)((b*SS + s)*AA);
    float u[AA];
    #pragma unroll
    for(int a=0;a<AA;a++){
      unsigned g = base + a;
      uint32_t o0, o1, bits;
      threefry2x32(0u, g, o0, o1); bits = o0 ^ o1;
      u[a] = bits_to_unit(bits);
    }
    int ord[AA];
    #pragma unroll
    for(int i=0;i<AA;i++) ord[i]=i;
    for(int i=1;i<AA;i++){
      int oi = ord[i]; float ku = u[oi]; int j=i;
      while(j>0 && u[ord[j-1]] > ku){ ord[j]=ord[j-1]; j--; }
      ord[j]=oi;
    }
    #pragma unroll
    for(int r=0;r<AA;r++) s_inv[s][ord[r]] = r;
    #pragma unroll
    for(int i=0;i<AA;i++) g_pos[base + i] = (unsigned char)ord[i];
  }
  __syncthreads();
  for(int e=tid; e<SS*AA*NACT; e+=blockDim.x){
    int s  = e >> 7;
    int r  = e & 127;
    int j  = r >> 4;
    int na = r & 15;
    s_rq[e] = qs[b*(AA*NACT) + s_inv[s][j]*NACT + na];
  }
  __syncthreads();

  const int sgrp = tid >> 6;       // 4 s per group
  const int cg   = tid & 63;
  const int kblk = cg >> 2;
  const int kp   = cg & 3;
  const int c0   = kblk*16 + kp*2;

  float2 baseA = *(const float2*)&g_sW1[b*EM + c0];
  float2 baseB = *(const float2*)&g_sW1[b*EM + c0 + 8];
  float acc[4][4];
  #pragma unroll
  for(int sl=0;sl<4;sl++){
    acc[sl][0]=baseA.x; acc[sl][1]=baseA.y;
    acc[sl][2]=baseB.x; acc[sl][3]=baseB.y;
  }

  for(int j=0;j<AA;j++){
    #pragma unroll
    for(int na=0;na<NACT;na++){
      const float* wr = &W1[(SD + j*NACT + na)*EM + c0];
      float2 wA = *(const float2*)wr;
      float2 wB = *(const float2*)(wr+8);
      #pragma unroll
      for(int sl=0;sl<4;sl++){
        float q = s_rq[(sgrp*4+sl)*128 + j*16 + na];
        acc[sl][0] = fmaf(q, wA.x, acc[sl][0]);
        acc[sl][1] = fmaf(q, wA.y, acc[sl][1]);
        acc[sl][2] = fmaf(q, wB.x, acc[sl][2]);
        acc[sl][3] = fmaf(q, wB.y, acc[sl][3]);
      }
    }
    const int lane = j*4 + kp;
    #pragma unroll
    for(int p=0;p<2;p++){
      int mblk = sgrp*2 + p;
      float r0c0 = fmaxf(acc[2*p][0],0.f),   r0c1 = fmaxf(acc[2*p][1],0.f);
      float r0c2 = fmaxf(acc[2*p][2],0.f),   r0c3 = fmaxf(acc[2*p][3],0.f);
      float r1c0 = fmaxf(acc[2*p+1][0],0.f), r1c1 = fmaxf(acc[2*p+1][1],0.f);
      float r1c2 = fmaxf(acc[2*p+1][2],0.f), r1c3 = fmaxf(acc[2*p+1][3],0.f);
      uint32_t h00,l00,h01,l01,h02,l02,h03,l03;
      uint32_t h10,l10,h11,l11,h12,l12,h13,l13;
      split_bf16(r0c0,h00,l00); split_bf16(r0c1,h01,l01);
      split_bf16(r0c2,h02,l02); split_bf16(r0c3,h03,l03);
      split_bf16(r1c0,h10,l10); split_bf16(r1c1,h11,l11);
      split_bf16(r1c2,h12,l12); split_bf16(r1c3,h13,l13);
      uint4 hv, lv;
      hv.x = h00 | (h01<<16);
      hv.y = h10 | (h11<<16);
      hv.z = h02 | (h03<<16);
      hv.w = h12 | (h13<<16);
      lv.x = l00 | (l01<<16);
      lv.y = l10 | (l11<<16);
      lv.z = l02 | (l03<<16);
      lv.w = l12 | (l13<<16);
      size_t aidx = ((((size_t)b*8 + mblk)*16 + kblk)*32 + lane)*4;
      *(uint4*)&g_Ah[aidx] = hv;
      *(uint4*)&g_Al[aidx] = lv;
    }
  }
}

// ============ K3: HMMA GEMM2, 2 mblk x 8 nb per warp ============
__global__ void __launch_bounds__(512,1) k3_mma(const float* __restrict__ b2,
                  const float* __restrict__ W3, const float* __restrict__ b3){
  __shared__ uint32_t sB[2][4096];
  __shared__ float b2s[256], w3s[256];
  __shared__ float sred[128][5];
  const int tid   = threadIdx.x;
  const int lane  = tid & 31;
  const int warp  = tid >> 5;      // 0..15
  const int mpair = warp >> 2;     // 0..3 -> mblk = mpair*2 + i
  const int ngrp  = warp & 3;      // 0..3 -> ng = ngrp*8 + nb
  const int b     = blockIdx.x;

  if (tid < 256){ b2s[tid] = b2[tid]; w3s[tid] = W3[tid]; }
  {
    const uint4* src = (const uint4*)g_B;
    uint4* dst = (uint4*)sB[0];
    dst[tid*2]   = src[tid*2];
    dst[tid*2+1] = src[tid*2+1];
  }

  float d[2][8][4];
  #pragma unroll
  for(int i=0;i<2;i++)
    #pragma unroll
    for(int nb=0;nb<8;nb++){ d[i][nb][0]=0.f; d[i][nb][1]=0.f; d[i][nb][2]=0.f; d[i][nb][3]=0.f; }

  uint32_t ah[2][4], al[2][4];
  #pragma unroll
  for(int i=0;i<2;i++){
    size_t a0 = ((((size_t)b*8 + (mpair*2+i))*16 + 0)*32 + lane)*4;
    *(uint4*)ah[i] = *(const uint4*)&g_Ah[a0];
    *(uint4*)al[i] = *(const uint4*)&g_Al[a0];
  }
  __syncthreads();

  for(int kb=0; kb<16; kb++){
    uint4 bs0, bs1;
    uint32_t ahn[2][4], aln[2][4];
    if (kb < 15){
      const uint4* src = (const uint4*)(g_B + (kb+1)*4096);
      bs0 = src[tid*2];
      bs1 = src[tid*2+1];
      #pragma unroll
      for(int i=0;i<2;i++){
        size_t an = ((((size_t)b*8 + (mpair*2+i))*16 + (kb+1))*32 + lane)*4;
        *(uint4*)ahn[i] = *(const uint4*)&g_Ah[an];
        *(uint4*)aln[i] = *(const uint4*)&g_Al[an];
      }
    }
    const uint32_t* cur = sB[kb&1];
    #pragma unroll
    for(int nb=0; nb<8; nb++){
      int ng = ngrp*8 + nb;
      uint4 bb = *(const uint4*)&cur[(ng*32 + lane)*4];
      #pragma unroll
      for(int i=0;i<2;i++){
        mma16816(d[i][nb], ah[i], bb.x, bb.y);  // ah*bh
        mma16816(d[i][nb], al[i], bb.x, bb.y);  // al*bh
        mma16816(d[i][nb], ah[i], bb.z, bb.w);  // ah*bl
      }
    }
    if (kb < 15){
      uint4* dst = (uint4*)sB[(kb+1)&1];
      dst[tid*2]   = bs0;
      dst[tid*2+1] = bs1;
      #pragma unroll
      for(int i=0;i<2;i++){
        #pragma unroll
        for(int r=0;r<4;r++){ ah[i][r]=ahn[i][r]; al[i][r]=aln[i][r]; }
      }
    }
    __syncthreads();
  }

  // epilogue: relu(d + b2) dot W3, quad-reduce across lane&3 (columns) via shfl
  float p[2][2];
  p[0][0]=0.f; p[0][1]=0.f; p[1][0]=0.f; p[1][1]=0.f;
  #pragma unroll
  for(int nb=0; nb<8; nb++){
    int c0 = (ngrp*8 + nb)*8 + (lane&3)*2;
    float w0 = w3s[c0], w1 = w3s[c0+1];
    float bb0 = b2s[c0], bb1 = b2s[c0+1];
    #pragma unroll
    for(int i=0;i<2;i++){
      p[i][0] += fmaxf(d[i][nb][0]+bb0,0.f)*w0 + fmaxf(d[i][nb][1]+bb1,0.f)*w1;
      p[i][1] += fmaxf(d[i][nb][2]+bb0,0.f)*w0 + fmaxf(d[i][nb][3]+bb1,0.f)*w1;
    }
  }
  #pragma unroll
  for(int i=0;i<2;i++){
    #pragma unroll
    for(int h=0;h<2;h++){
      p[i][h] += __shfl_xor_sync(0xFFFFFFFFu, p[i][h], 1);
      p[i][h] += __shfl_xor_sync(0xFFFFFFFFu, p[i][h], 2);
    }
  }
  if ((lane & 3) == 0){
    #pragma unroll
    for(int i=0;i<2;i++){
      int rbase = (mpair*2+i)*16 + (lane>>2);
      sred[rbase  ][ngrp] = p[i][0];
      sred[rbase+8][ngrp] = p[i][1];
    }
  }
  __syncthreads();
  if (tid < 128){
    g_adv[b*128 + tid] = b3[0] + sred[tid][0] + sred[tid][1] + sred[tid][2] + sred[tid][3];
  }
}

// ============ K4: shapley ============
__global__ void k4_out(float* __restrict__ out){
  int idx = blockIdx.x*blockDim.x + threadIdx.x;
  if(idx >= NB*AA) return;
  int b = idx >> 3, i = idx & 7;
  float sum = 0.f;
  #pragma unroll
  for(int s=0;s<SS;s++){
    int base = (b*SS+s)*AA;
    sum += g_adv[base + (int)g_pos[base+i]];
  }
  out[idx] = g_v[b] + sum * (1.0f/16.0f);
}

extern "C" void kernel_launch(void* const* d_in, const int* in_sizes, int n_in,
                              void* d_out, int out_size){
  const float* states   = (const float*)d_in[0];
  const float* agent_qs = (const float*)d_in[1];
  const float* W1  = (const float*)d_in[2];
  const float* b1  = (const float*)d_in[3];
  const float* W2  = (const float*)d_in[4];
  const float* b2  = (const float*)d_in[5];
  const float* W3  = (const float*)d_in[6];
  const float* b3  = (const float*)d_in[7];
  const float* Vw1 = (const float*)d_in[8];
  const float* Vb1 = (const float*)d_in[9];
  const float* Vw2 = (const float*)d_in[10];
  const float* Vb2 = (const float*)d_in[11];
  float* out = (float*)d_out;

  k0_prepW2<<<128, 256>>>(W2);
  k1_state <<<NB, EM>>>(states, W1, b1, Vw1, Vb1, Vw2, Vb2);
  k2_layer1<<<NB, 256>>>(agent_qs, W1);
  k3_mma   <<<NB, 512>>>(b2, W3, b3);
  k4_out   <<<(NB*AA + 255)/256, 256>>>(out);
}

// round 8
// speedup vs baseline: 1.2146x; 1.2146x over previous
#include <cuda_runtime.h>
#include <cuda_bf16.h>
#include <stdint.h>

typedef unsigned long long ull;

#define NB   1024
#define SS   16
#define AA   8
#define NACT 16
#define SD   256
#define EM   256
#define NROWS (NB*SS*AA)   // 131072

// ---------------- device scratch ----------------
__device__ float g_sW1[NB*EM];
__device__ float g_v[NB];
__device__ unsigned char g_pos[NROWS];
// h1 A-fragments: [b][mblk(8)][kblk(16)][lane(32)][reg(4)] u32, hi and lo
__device__ uint32_t g_Ah[(size_t)NB*8*16*32*4];
__device__ uint32_t g_Al[(size_t)NB*8*16*32*4];
// W2 B-fragments: [kblk(16)][nblk(32)][lane(32)][reg(2)] u32 (R5 layout)
__device__ uint32_t g_Bh[16*32*32*2];
__device__ uint32_t g_Bl[16*32*32*2];

// ---------------- threefry2x32 (JAX exact, key(42)) ----------------
__device__ __forceinline__ uint32_t rotl(uint32_t x, int r){ return (x<<r)|(x>>(32-r)); }
__device__ __forceinline__ void threefry2x32(uint32_t c0, uint32_t c1, uint32_t &o0, uint32_t &o1){
  const uint32_t k0 = 0u, k1v = 42u, k2 = 0u ^ 42u ^ 0x1BD11BDAu;
  uint32_t x0 = c0 + k0;
  uint32_t x1 = c1 + k1v;
#define TF_R(rot) { x0 += x1; x1 = rotl(x1, rot); x1 ^= x0; }
  TF_R(13) TF_R(15) TF_R(26) TF_R(6)
  x0 += k1v; x1 += k2 + 1u;
  TF_R(17) TF_R(29) TF_R(16) TF_R(24)
  x0 += k2;  x1 += k0 + 2u;
  TF_R(13) TF_R(15) TF_R(26) TF_R(6)
  x0 += k0;  x1 += k1v + 3u;
  TF_R(17) TF_R(29) TF_R(16) TF_R(24)
  x0 += k1v; x1 += k2 + 4u;
  TF_R(13) TF_R(15) TF_R(26) TF_R(6)
  x0 += k2;  x1 += k0 + 5u;
#undef TF_R
  o0 = x0; o1 = x1;
}
__device__ __forceinline__ float bits_to_unit(uint32_t bits){
  return __uint_as_float(0x3f800000u | (bits >> 9)) - 1.0f;
}

__device__ __forceinline__ void split_bf16(float v, uint32_t &h, uint32_t &l){
  __nv_bfloat16 hb = __float2bfloat16(v);
  float lf = v - __bfloat162float(hb);
  __nv_bfloat16 lb = __float2bfloat16(lf);
  h = (uint32_t)__bfloat16_as_ushort(hb);
  l = (uint32_t)__bfloat16_as_ushort(lb);
}

__device__ __forceinline__ void mma16816(float* d, const uint32_t* a, uint32_t b0, uint32_t b1){
  asm volatile("mma.sync.aligned.m16n8k16.row.col.f32.bf16.bf16.f32 "
    "{%0,%1,%2,%3}, {%4,%5,%6,%7}, {%8,%9}, {%0,%1,%2,%3};"
    : "+f"(d[0]),"+f"(d[1]),"+f"(d[2]),"+f"(d[3])
    : "r"(a[0]),"r"(a[1]),"r"(a[2]),"r"(a[3]), "r"(b0),"r"(b1));
}

// ============ K0: W2 -> B fragments (R5 layout) ============
__global__ void k0_prepW2(const float* __restrict__ W2){
  int idx = blockIdx.x*256 + threadIdx.x;   // 32768
  int kp = idx >> 8, n = idx & 255;
  int k = kp*2;
  float v0 = W2[k*EM + n];
  float v1 = W2[(k+1)*EM + n];
  uint32_t h0,l0,h1,l1;
  split_bf16(v0,h0,l0); split_bf16(v1,h1,l1);
  uint32_t hi = h0 | (h1<<16);
  uint32_t lo = l0 | (l1<<16);
  int kblk = kp>>3;
  int reg  = (kp>>2)&1;
  int lane = (n&7)*4 + (kp&3);
  int nblk = n>>3;
  int bidx = ((kblk*32+nblk)*32+lane)*2 + reg;
  g_Bh[bidx] = hi;
  g_Bl[bidx] = lo;
}

// ============ K1: per-b state terms, 8 b per CTA (W-column reuse) ============
__global__ void __launch_bounds__(256) k1_state(const float* __restrict__ st,
                         const float* __restrict__ W1,
                         const float* __restrict__ b1, const float* __restrict__ Vw1,
                         const float* __restrict__ Vb1, const float* __restrict__ Vw2,
                         const float* __restrict__ Vb2){
  const int b0 = blockIdx.x * 8;
  const int n  = threadIdx.x;
  __shared__ float s_st[8][SD];
  __shared__ float red[8][EM];
  #pragma unroll
  for(int bi=0;bi<8;bi++) s_st[bi][n] = st[(b0+bi)*SD + n];
  __syncthreads();
  float acc[8], accv[8];
  float bb1 = b1[n], vbb = Vb1[n];
  #pragma unroll
  for(int bi=0;bi<8;bi++){ acc[bi]=bb1; accv[bi]=vbb; }
  for(int k=0;k<SD;k++){
    float w  = W1 [k*EM + n];
    float vw = Vw1[k*EM + n];
    #pragma unroll
    for(int bi=0;bi<8;bi++){
      float sv = s_st[bi][k];
      acc[bi]  = fmaf(sv, w,  acc[bi]);
      accv[bi] = fmaf(sv, vw, accv[bi]);
    }
  }
  float vw2 = Vw2[n];
  #pragma unroll
  for(int bi=0;bi<8;bi++){
    g_sW1[(b0+bi)*EM + n] = acc[bi];
    red[bi][n] = fmaxf(accv[bi], 0.f) * vw2;
  }
  __syncthreads();
  int w = n >> 5, l = n & 31;
  // 8 warps, one b each
  float s = 0.f;
  #pragma unroll
  for(int t=0;t<8;t++) s += red[w][l + t*32];
  #pragma unroll
  for(int off=16; off>0; off>>=1) s += __shfl_xor_sync(0xFFFFFFFFu, s, off);
  if (l == 0) g_v[b0 + w] = s + Vb2[0];
}

// ============ K2: RNG + perms + prefix layer-1, 4 b per CTA -> A fragments ============
__global__ void __launch_bounds__(256) k2_layer1(const float* __restrict__ qs,
                                                 const float* __restrict__ W1){
  const int b0 = blockIdx.x * 4;
  const int tid = threadIdx.x;
  __shared__ int   s_inv[4][SS][AA];
  __shared__ float s_rq[4][SS*AA*NACT];   // 32 KB

  if(tid < 64){
    int bq = tid >> 4, s = tid & 15;
    unsigned base = (unsigned)(((b0+bq)*SS + s)*AA);
    float u[AA];
    #pragma unroll
    for(int a=0;a<AA;a++){
      unsigned g = base + a;
      uint32_t o0, o1;
      threefry2x32(0u, g, o0, o1);
      u[a] = bits_to_unit(o0 ^ o1);
    }
    int ord[AA];
    #pragma unroll
    for(int i=0;i<AA;i++) ord[i]=i;
    for(int i=1;i<AA;i++){
      int oi = ord[i]; float ku = u[oi]; int j=i;
      while(j>0 && u[ord[j-1]] > ku){ ord[j]=ord[j-1]; j--; }
      ord[j]=oi;
    }
    #pragma unroll
    for(int r=0;r<AA;r++) s_inv[bq][s][ord[r]] = r;
    #pragma unroll
    for(int i=0;i<AA;i++) g_pos[base + i] = (unsigned char)ord[i];
  }
  __syncthreads();
  for(int e=tid; e<4*SS*AA*NACT; e+=256){
    int bq = e >> 11;
    int r2 = e & 2047;
    int s  = r2 >> 7;
    int r  = r2 & 127;
    int j  = r >> 4;
    int na = r & 15;
    s_rq[bq][s*128 + r] = qs[(b0+bq)*(AA*NACT) + s_inv[bq][s][j]*NACT + na];
  }
  __syncthreads();

  const int sgrp = tid >> 6;       // 4 s per group per b
  const int cg   = tid & 63;
  const int kblk = cg >> 2;
  const int kp   = cg & 3;
  const int c0   = kblk*16 + kp*2;

  float acc[4][4][4];              // [bq][slq][col]
  #pragma unroll
  for(int bq=0;bq<4;bq++){
    float2 bA = *(const float2*)&g_sW1[(b0+bq)*EM + c0];
    float2 bB = *(const float2*)&g_sW1[(b0+bq)*EM + c0 + 8];
    #pragma unroll
    for(int sl=0;sl<4;sl++){
      acc[bq][sl][0]=bA.x; acc[bq][sl][1]=bA.y;
      acc[bq][sl][2]=bB.x; acc[bq][sl][3]=bB.y;
    }
  }

  for(int j=0;j<AA;j++){
    #pragma unroll
    for(int na=0;na<NACT;na++){
      const float* wr = &W1[(SD + j*NACT + na)*EM + c0];
      float2 wA = *(const float2*)wr;
      float2 wB = *(const float2*)(wr+8);
      #pragma unroll
      for(int bq=0;bq<4;bq++){
        #pragma unroll
        for(int sl=0;sl<4;sl++){
          float q = s_rq[bq][(sgrp*4+sl)*128 + j*16 + na];
          acc[bq][sl][0] = fmaf(q, wA.x, acc[bq][sl][0]);
          acc[bq][sl][1] = fmaf(q, wA.y, acc[bq][sl][1]);
          acc[bq][sl][2] = fmaf(q, wB.x, acc[bq][sl][2]);
          acc[bq][sl][3] = fmaf(q, wB.y, acc[bq][sl][3]);
        }
      }
    }
    const int lane = j*4 + kp;
    #pragma unroll
    for(int bq=0;bq<4;bq++){
      #pragma unroll
      for(int p=0;p<2;p++){
        int mblk = sgrp*2 + p;
        float r0c0 = fmaxf(acc[bq][2*p][0],0.f),   r0c1 = fmaxf(acc[bq][2*p][1],0.f);
        float r0c2 = fmaxf(acc[bq][2*p][2],0.f),   r0c3 = fmaxf(acc[bq][2*p][3],0.f);
        float r1c0 = fmaxf(acc[bq][2*p+1][0],0.f), r1c1 = fmaxf(acc[bq][2*p+1][1],0.f);
        float r1c2 = fmaxf(acc[bq][2*p+1][2],0.f), r1c3 = fmaxf(acc[bq][2*p+1][3],0.f);
        uint32_t h00,l00,h01,l01,h02,l02,h03,l03;
        uint32_t h10,l10,h11,l11,h12,l12,h13,l13;
        split_bf16(r0c0,h00,l00); split_bf16(r0c1,h01,l01);
        split_bf16(r0c2,h02,l02); split_bf16(r0c3,h03,l03);
        split_bf16(r1c0,h10,l10); split_bf16(r1c1,h11,l11);
        split_bf16(r1c2,h12,l12); split_bf16(r1c3,h13,l13);
        uint4 hv, lv;
        hv.x = h00 | (h01<<16);
        hv.y = h10 | (h11<<16);
        hv.z = h02 | (h03<<16);
        hv.w = h12 | (h13<<16);
        lv.x = l00 | (l01<<16);
        lv.y = l10 | (l11<<16);
        lv.z = l02 | (l03<<16);
        lv.w = l12 | (l13<<16);
        size_t aidx = ((((size_t)(b0+bq)*8 + mblk)*16 + kblk)*32 + lane)*4;
        *(uint4*)&g_Ah[aidx] = hv;
        *(uint4*)&g_Al[aidx] = lv;
      }
    }
  }
}

// ============ K3: HMMA GEMM2 (exact R5 layout) + fused shapley output ============
__global__ void __launch_bounds__(512,1) k3_mma(const float* __restrict__ b2,
                  const float* __restrict__ W3, const float* __restrict__ b3,
                  float* __restrict__ out){
  __shared__ uint32_t sB[2][2][2048];
  __shared__ float b2s[256], w3s[256];
  __shared__ float sred[128][9];
  __shared__ float advs[128];
  const int tid  = threadIdx.x;
  const int lane = tid & 31;
  const int warp = tid >> 5;
  const int mblk = warp & 7;
  const int nh   = warp >> 3;
  const int b    = blockIdx.x;

  if (tid < 256){ b2s[tid] = b2[tid]; w3s[tid] = W3[tid]; }
  {
    uint4 h = *(const uint4*)&g_Bh[tid*4];
    uint4 l = *(const uint4*)&g_Bl[tid*4];
    *(uint4*)&sB[0][0][tid*4] = h;
    *(uint4*)&sB[0][1][tid*4] = l;
  }

  float d[16][4];
  #pragma unroll
  for(int i=0;i<16;i++){ d[i][0]=0.f; d[i][1]=0.f; d[i][2]=0.f; d[i][3]=0.f; }

  uint32_t ah[4], al[4];
  {
    size_t a0 = ((((size_t)b*8 + mblk)*16 + 0)*32 + lane)*4;
    *(uint4*)ah = *(const uint4*)&g_Ah[a0];
    *(uint4*)al = *(const uint4*)&g_Al[a0];
  }
  __syncthreads();

  for(int kb=0; kb<16; kb++){
    uint4 nh4, nl4;
    uint32_t ahn[4], aln[4];
    if (kb < 15){
      nh4 = *(const uint4*)&g_Bh[(kb+1)*2048 + tid*4];
      nl4 = *(const uint4*)&g_Bl[(kb+1)*2048 + tid*4];
      size_t an = ((((size_t)b*8 + mblk)*16 + (kb+1))*32 + lane)*4;
      *(uint4*)ahn = *(const uint4*)&g_Ah[an];
      *(uint4*)aln = *(const uint4*)&g_Al[an];
    }
    const uint32_t* curh = sB[kb&1][0];
    const uint32_t* curl = sB[kb&1][1];
    #pragma unroll
    for(int nb=0; nb<16; nb++){
      int ng  = nh*16 + nb;
      int off = (ng*32 + lane)*2;
      uint2 bh = *(const uint2*)&curh[off];
      uint2 bl = *(const uint2*)&curl[off];
      mma16816(d[nb], ah, bh.x, bh.y);
      mma16816(d[nb], al, bh.x, bh.y);
      mma16816(d[nb], ah, bl.x, bl.y);
    }
    if (kb < 15){
      *(uint4*)&sB[(kb+1)&1][0][tid*4] = nh4;
      *(uint4*)&sB[(kb+1)&1][1][tid*4] = nl4;
      #pragma unroll
      for(int i=0;i<4;i++){ ah[i]=ahn[i]; al[i]=aln[i]; }
    }
    __syncthreads();
  }

  // epilogue: relu(d + b2) dot W3
  float p0 = 0.f, p1 = 0.f;
  #pragma unroll
  for(int nb=0; nb<16; nb++){
    int c0 = (nh*16 + nb)*8 + (lane&3)*2;
    float w0 = w3s[c0], w1 = w3s[c0+1];
    float bb0 = b2s[c0], bb1 = b2s[c0+1];
    p0 += fmaxf(d[nb][0]+bb0, 0.f)*w0 + fmaxf(d[nb][1]+bb1, 0.f)*w1;
    p1 += fmaxf(d[nb][2]+bb0, 0.f)*w0 + fmaxf(d[nb][3]+bb1, 0.f)*w1;
  }
  // quad-reduce over lane&3 (columns)
  p0 += __shfl_xor_sync(0xFFFFFFFFu, p0, 1);
  p0 += __shfl_xor_sync(0xFFFFFFFFu, p0, 2);
  p1 += __shfl_xor_sync(0xFFFFFFFFu, p1, 1);
  p1 += __shfl_xor_sync(0xFFFFFFFFu, p1, 2);
  if ((lane & 3) == 0){
    int r0 = mblk*16 + (lane>>2);
    sred[r0  ][nh] = p0;
    sred[r0+8][nh] = p1;
  }
  __syncthreads();
  if (tid < 128){
    advs[tid] = b3[0] + sred[tid][0] + sred[tid][1];
  }
  __syncthreads();
  // fused k4: shapley[b,i] = v[b] + mean_s advs[s*8 + pos[b,s,i]]
  if (tid < 8){
    float sum = 0.f;
    #pragma unroll
    for(int s=0;s<SS;s++){
      sum += advs[s*8 + (int)g_pos[b*128 + s*8 + tid]];
    }
    out[b*8 + tid] = g_v[b] + sum * (1.0f/16.0f);
  }
}

extern "C" void kernel_launch(void* const* d_in, const int* in_sizes, int n_in,
                              void* d_out, int out_size){
  const float* states   = (const float*)d_in[0];
  const float* agent_qs = (const float*)d_in[1];
  const float* W1  = (const float*)d_in[2];
  const float* b1  = (const float*)d_in[3];
  const float* W2  = (const float*)d_in[4];
  const float* b2  = (const float*)d_in[5];
  const float* W3  = (const float*)d_in[6];
  const float* b3  = (const float*)d_in[7];
  const float* Vw1 = (const float*)d_in[8];
  const float* Vb1 = (const float*)d_in[9];
  const float* Vw2 = (const float*)d_in[10];
  const float* Vb2 = (const float*)d_in[11];
  float* out = (float*)d_out;

  k0_prepW2<<<128, 256>>>(W2);
  k1_state <<<NB/8, 256>>>(states, W1, b1, Vw1, Vb1, Vw2, Vb2);
  k2_layer1<<<NB/4, 256>>>(agent_qs, W1);
  k3_mma   <<<NB, 512>>>(b2, W3, b3, out);
}